// round 14
// baseline (speedup 1.0000x reference)
#include <cuda_runtime.h>

#define FULL 0xffffffffu

constexpr int P = 4096, F = 64, HG = 64, C = 64, T = 32, E = 65536, HOUT = 12;
constexpr float EPS = 1e-5f;

// ---- scratch (static device globals; no allocation at runtime) ----
__device__ float  g_Xt[T * P * F];     // X transposed: [t][p][f]
__device__ float  g_hl[T * P * HG];    // x @ Wl
__device__ float  g_hr[T * P * HG];    // x @ Wr
__device__ int    g_deg[T * P];
__device__ int    g_offs[T * P];
__device__ int    g_cur[T * P];        // absolute write cursor (init = offs)
__device__ float  g_sc[T * E];         // raw scores, NATURAL edge order
__device__ float2 g_epair[T * E];      // CSR-ordered (src_as_float, score)
__device__ float  g_Xhat[T * P * HG];  // relu(GAT out)
__device__ float  g_yn[P * T * C];     // LayerNormed y, [p][t][c]

__device__ __forceinline__ float leaky(float x) { return x > 0.f ? x : 0.2f * x; }

__device__ __forceinline__ float warp_sum(float v) {
    v += __shfl_xor_sync(FULL, v, 16);
    v += __shfl_xor_sync(FULL, v, 8);
    v += __shfl_xor_sync(FULL, v, 4);
    v += __shfl_xor_sync(FULL, v, 2);
    v += __shfl_xor_sync(FULL, v, 1);
    return v;
}

__device__ __forceinline__ float warp_max(float v) {
    v = fmaxf(v, __shfl_xor_sync(FULL, v, 16));
    v = fmaxf(v, __shfl_xor_sync(FULL, v, 8));
    v = fmaxf(v, __shfl_xor_sync(FULL, v, 4));
    v = fmaxf(v, __shfl_xor_sync(FULL, v, 2));
    v = fmaxf(v, __shfl_xor_sync(FULL, v, 1));
    return v;
}

// dual FMA on float2 (plain C++; compiler emits 2x FFMA)
__device__ __forceinline__ void ffma2(float2& d, float b, float2 w) {
    d.x = fmaf(b, w.x, d.x);
    d.y = fmaf(b, w.y, d.y);
}

// ---- K1: zero + histogram + exclusive scan; cursor pre-set to offs ----
__global__ void __launch_bounds__(1024) k_build(const int* __restrict__ ei) {
    __shared__ int h[P];
    __shared__ int ssum[1024];
    int t = blockIdx.x, tid = threadIdx.x;
    for (int i = tid; i < P; i += 1024) h[i] = 0;
    __syncthreads();
    const int* dstp = ei + (size_t)t * 2 * E + E;
#pragma unroll 4
    for (int k = 0; k < 64; k++) atomicAdd(&h[dstp[k * 1024 + tid]], 1);
    __syncthreads();
    int base = tid * 4;
    int d0 = h[base], d1 = h[base + 1], d2 = h[base + 2], d3 = h[base + 3];
    ssum[tid] = d0 + d1 + d2 + d3;
    __syncthreads();
    for (int off = 1; off < 1024; off <<= 1) {
        int v = (tid >= off) ? ssum[tid - off] : 0;
        __syncthreads();
        ssum[tid] += v;
        __syncthreads();
    }
    int excl = tid ? ssum[tid - 1] : 0;
    int gb = t * P + base;
    int o0 = excl, o1 = excl + d0, o2 = o1 + d1, o3 = o2 + d2;
    g_offs[gb] = o0; g_offs[gb + 1] = o1; g_offs[gb + 2] = o2; g_offs[gb + 3] = o3;
    g_deg[gb] = d0;  g_deg[gb + 1] = d1;  g_deg[gb + 2] = d2;  g_deg[gb + 3] = d3;
    g_cur[gb] = o0;  g_cur[gb + 1] = o1;  g_cur[gb + 2] = o2;  g_cur[gb + 3] = o3;
}

// ---- K2: transpose X[1,P,F,T] -> Xt[t][p][f] ----
__global__ void k_transpose(const float* __restrict__ X) {
    __shared__ float sm[64 * 33];
    int p = blockIdx.x;
    const float* xp = X + (size_t)p * (F * T);
    for (int idx = threadIdx.x; idx < F * T; idx += blockDim.x) {
        int f = idx >> 5, t = idx & 31;
        sm[f * 33 + t] = xp[idx];
    }
    __syncthreads();
    for (int idx = threadIdx.x; idx < F * T; idx += blockDim.x) {
        int t = idx >> 6, f = idx & 63;
        g_Xt[((size_t)t * P + p) * 64 + f] = sm[f * 33 + t];
    }
}

// ---- K3: hl = x@Wl, hr = x@Wr  (warp per 8 rows, float2 LDS) ----
__global__ void __launch_bounds__(256) k_proj(const float* __restrict__ Wl,
                                              const float* __restrict__ Wr) {
    __shared__ float2 sWl[2048], sWr[2048];   // [k][col-pair] (row-major (F,HG))
    for (int i = threadIdx.x; i < 2048; i += blockDim.x) {
        sWl[i] = ((const float2*)Wl)[i];
        sWr[i] = ((const float2*)Wr)[i];
    }
    __syncthreads();
    int w = blockIdx.x * 8 + (threadIdx.x >> 5);
    int lane = threadIdx.x & 31;
    int row0 = w * 8;
    float x0[8], x1[8];
#pragma unroll
    for (int r = 0; r < 8; r++) {
        const float* x = g_Xt + (size_t)(row0 + r) * 64;
        x0[r] = x[lane]; x1[r] = x[lane + 32];
    }
    float2 al[8], ar[8];
#pragma unroll
    for (int r = 0; r < 8; r++) { al[r] = make_float2(0.f, 0.f); ar[r] = make_float2(0.f, 0.f); }
#pragma unroll 4
    for (int k = 0; k < 32; k++) {
        float2 wl = sWl[k * 32 + lane], wr = sWr[k * 32 + lane];
#pragma unroll
        for (int r = 0; r < 8; r++) {
            float b = __shfl_sync(FULL, x0[r], k);
            ffma2(al[r], b, wl);
            ffma2(ar[r], b, wr);
        }
    }
#pragma unroll 4
    for (int k = 0; k < 32; k++) {
        float2 wl = sWl[(k + 32) * 32 + lane], wr = sWr[(k + 32) * 32 + lane];
#pragma unroll
        for (int r = 0; r < 8; r++) {
            float b = __shfl_sync(FULL, x1[r], k);
            ffma2(al[r], b, wl);
            ffma2(ar[r], b, wr);
        }
    }
#pragma unroll
    for (int r = 0; r < 8; r++) {
        ((float2*)g_hl)[(size_t)(row0 + r) * 32 + lane] = al[r];
        ((float2*)g_hr)[(size_t)(row0 + r) * 32 + lane] = ar[r];
    }
}

// ---- K4: scoring in NATURAL edge order (coalesced ei reads, no CSR dep) ----
// 8 lanes per edge, 4 edges per warp, float4 feature loads.
__global__ void __launch_bounds__(256) k_score(const int* __restrict__ ei,
                                               const float* __restrict__ att) {
    int lane = threadIdx.x & 31;
    int oct = lane >> 3, sub = lane & 7;
    int warp = blockIdx.x * 8 + (threadIdx.x >> 5);
    int t = warp >> 14;                     // E/4 = 16384 warps per t
    int e = (warp & 16383) * 4 + oct;
    int src = ei[(size_t)t * 2 * E + e];        // broadcast within oct
    int dst = ei[(size_t)t * 2 * E + E + e];
    const float4* hl4 = (const float4*)g_hl + ((size_t)t * P + src) * 16;
    const float4* hr4 = (const float4*)g_hr + ((size_t)t * P + dst) * 16;
    const float4* at4 = (const float4*)att;
    float sc = 0.f;
#pragma unroll
    for (int k = 0; k < 2; k++) {
        int idx = sub + 8 * k;
        float4 a = at4[idx];
        float4 vl = hl4[idx];
        float4 vr = hr4[idx];
        sc += leaky(vl.x + vr.x) * a.x + leaky(vl.y + vr.y) * a.y
            + leaky(vl.z + vr.z) * a.z + leaky(vl.w + vr.w) * a.w;
    }
    sc += __shfl_xor_sync(FULL, sc, 4);
    sc += __shfl_xor_sync(FULL, sc, 2);
    sc += __shfl_xor_sync(FULL, sc, 1);
    if (sub == 0) g_sc[(size_t)t * E + e] = sc;
}

// ---- K5: place packed (src, score) into CSR buckets (one STG.64 per edge) ----
__global__ void k_place(const int* __restrict__ ei) {
    int gid = blockIdx.x * blockDim.x + threadIdx.x;
    int t = gid >> 16, e = gid & (E - 1);
    int src = ei[(size_t)t * 2 * E + e];
    int dst = ei[(size_t)t * 2 * E + E + e];
    float sc = g_sc[(size_t)t * E + e];
    int slot = atomicAdd(&g_cur[t * P + dst], 1);   // absolute (cursor = offs)
    g_epair[(size_t)t * E + slot] = make_float2(__int_as_float(src), sc);
}

// ---- K6: softmax + weighted gather, float4 x 2 edges/iter (warp per dst) ----
__global__ void __launch_bounds__(256) k_combine(const float* __restrict__ gat_b) {
    int lane = threadIdx.x & 31;
    int half = lane >> 4, hlane = lane & 15;
    int warp = blockIdx.x * 8 + (threadIdx.x >> 5);
    int t = warp >> 12;
    int start = g_offs[warp], deg = g_deg[warp];
    const float2* ep = g_epair + (size_t)t * E + start;
    const float4* hl4 = (const float4*)g_hl + (size_t)t * P * 16;
    float4 acc = make_float4(0.f, 0.f, 0.f, 0.f);
    float inv = 0.f;

    if (deg <= 32) {
        float2 pr = (lane < deg) ? ep[lane] : make_float2(0.f, -1e30f);
        int srcs = __float_as_int(pr.x);
        float mx = warp_max(pr.y);
        float wgt = (lane < deg) ? __expf(pr.y - mx) : 0.f;
        float s = warp_sum(wgt);
        if (lane >= deg) srcs = 0;
        // 2 edges per iter: half-warp h takes edge 2jj+h; invalid lanes w=0,row 0
#pragma unroll
        for (int jj = 0; jj < 16; jj++) {
            int j = jj * 2 + half;
            int sj = __shfl_sync(FULL, srcs, j);
            float wj = __shfl_sync(FULL, wgt, j);
            float4 v = hl4[(size_t)sj * 16 + hlane];
            acc.x += wj * v.x; acc.y += wj * v.y;
            acc.z += wj * v.z; acc.w += wj * v.w;
        }
        inv = (deg > 0) ? 1.f / s : 0.f;
    } else {
        float mx = -1e30f;
        for (int i = lane; i < deg; i += 32) mx = fmaxf(mx, ep[i].y);
        mx = warp_max(mx);
        float s = 0.f;
        for (int k = 0; k < deg; k += 32) {
            int n = min(32, deg - k);
            float2 pr = (lane < n) ? ep[k + lane] : make_float2(0.f, -1e30f);
            int srcs = (lane < n) ? __float_as_int(pr.x) : 0;
            float wgt = (lane < n) ? __expf(pr.y - mx) : 0.f;
            s += wgt;
#pragma unroll
            for (int jj = 0; jj < 16; jj++) {
                int j = jj * 2 + half;
                int sj = __shfl_sync(FULL, srcs, j);
                float wj = __shfl_sync(FULL, wgt, j);
                float4 v = hl4[(size_t)sj * 16 + hlane];
                acc.x += wj * v.x; acc.y += wj * v.y;
                acc.z += wj * v.z; acc.w += wj * v.w;
            }
        }
        s = warp_sum(s);
        inv = 1.f / s;
    }
    acc.x += __shfl_xor_sync(FULL, acc.x, 16);
    acc.y += __shfl_xor_sync(FULL, acc.y, 16);
    acc.z += __shfl_xor_sync(FULL, acc.z, 16);
    acc.w += __shfl_xor_sync(FULL, acc.w, 16);
    if (half == 0) {
        float4 gb = ((const float4*)gat_b)[hlane];
        float4 o;
        o.x = fmaxf(acc.x * inv + gb.x, 0.f);
        o.y = fmaxf(acc.y * inv + gb.y, 0.f);
        o.z = fmaxf(acc.z * inv + gb.z, 0.f);
        o.w = fmaxf(acc.w * inv + gb.w, 0.f);
        ((float4*)g_Xhat)[(size_t)warp * 16 + hlane] = o;
    }
}

// ---- K7: time conv + residual conv + relu + LayerNorm (warp per 8 rows) ----
__global__ void __launch_bounds__(256) k_epi(const float* __restrict__ Wt, const float* __restrict__ bt,
                                             const float* __restrict__ Wr_, const float* __restrict__ br,
                                             const float* __restrict__ lng, const float* __restrict__ lnb) {
    __shared__ float sWt[64 * 66], sWr[64 * 66];   // [h][c], pad 66
    for (int idx = threadIdx.x; idx < 4096; idx += blockDim.x) {
        int c = idx >> 6, h = idx & 63;
        sWt[h * 66 + c] = Wt[idx];                 // W_time (C, HG) row-major
        sWr[h * 66 + c] = Wr_[idx];                // W_res  (C, F)  row-major
    }
    __syncthreads();
    int w = blockIdx.x * 8 + (threadIdx.x >> 5);
    int lane = threadIdx.x & 31;
    int row0 = w * 8;
    int t = row0 >> 12;
    float xh0[8], xh1[8], xf0[8], xf1[8];
#pragma unroll
    for (int r = 0; r < 8; r++) {
        size_t base = (size_t)(row0 + r) * 64;
        xh0[r] = g_Xhat[base + lane]; xh1[r] = g_Xhat[base + lane + 32];
        xf0[r] = g_Xt[base + lane];   xf1[r] = g_Xt[base + lane + 32];
    }
    float2 th[8], rs[8];
#pragma unroll
    for (int r = 0; r < 8; r++) { th[r] = make_float2(0.f, 0.f); rs[r] = make_float2(0.f, 0.f); }
#pragma unroll 4
    for (int k = 0; k < 32; k++) {
        float2 wt = *(const float2*)(sWt + k * 66 + 2 * lane);
        float2 wr = *(const float2*)(sWr + k * 66 + 2 * lane);
#pragma unroll
        for (int r = 0; r < 8; r++) {
            float bh = __shfl_sync(FULL, xh0[r], k);
            float bf = __shfl_sync(FULL, xf0[r], k);
            ffma2(th[r], bh, wt);
            ffma2(rs[r], bf, wr);
        }
    }
#pragma unroll 4
    for (int k = 0; k < 32; k++) {
        float2 wt = *(const float2*)(sWt + (k + 32) * 66 + 2 * lane);
        float2 wr = *(const float2*)(sWr + (k + 32) * 66 + 2 * lane);
#pragma unroll
        for (int r = 0; r < 8; r++) {
            float bh = __shfl_sync(FULL, xh1[r], k);
            float bf = __shfl_sync(FULL, xf1[r], k);
            ffma2(th[r], bh, wt);
            ffma2(rs[r], bf, wr);
        }
    }
    float2 btc = ((const float2*)bt)[lane];
    float2 brc = ((const float2*)br)[lane];
    float2 g2 = ((const float2*)lng)[lane];
    float2 lb2 = ((const float2*)lnb)[lane];
    float bsx = btc.x + brc.x, bsy = btc.y + brc.y;
#pragma unroll
    for (int r = 0; r < 8; r++) {
        float y0 = fmaxf(th[r].x + rs[r].x + bsx, 0.f);
        float y1 = fmaxf(th[r].y + rs[r].y + bsy, 0.f);
        float mu = warp_sum(y0 + y1) * (1.f / 64.f);
        float d0 = y0 - mu, d1 = y1 - mu;
        float var = warp_sum(d0 * d0 + d1 * d1) * (1.f / 64.f);
        float rq = rsqrtf(var + EPS);
        int p = (row0 + r) & (P - 1);
        float2 yn2;
        yn2.x = d0 * rq * g2.x + lb2.x;
        yn2.y = d1 * rq * g2.y + lb2.y;
        ((float2*)(g_yn + (size_t)p * (T * C) + t * 64))[lane] = yn2;
    }
}

// ---- K8: final contraction out[p][o] = sum_{t,c} yn[p][t][c] * Wf[o][t][c] ----
__global__ void k_final(const float* __restrict__ Wf, const float* __restrict__ bf,
                        float* __restrict__ out) {
    int warp = blockIdx.x * (blockDim.x >> 5) + (threadIdx.x >> 5);
    int lane = threadIdx.x & 31;
    int p = warp;
    const float* y = g_yn + (size_t)p * (T * C);
    float acc[HOUT];
#pragma unroll
    for (int o = 0; o < HOUT; o++) acc[o] = 0.f;
    for (int idx = lane; idx < T * C; idx += 32) {
        float yv = y[idx];
#pragma unroll
        for (int o = 0; o < HOUT; o++) acc[o] += yv * __ldg(&Wf[o * (T * C) + idx]);
    }
    float myval = 0.f;
#pragma unroll
    for (int o = 0; o < HOUT; o++) {
        float v = warp_sum(acc[o]);
        if (lane == o) myval = v;
    }
    if (lane < HOUT) out[p * HOUT + lane] = myval + __ldg(&bf[lane]);
}

extern "C" void kernel_launch(void* const* d_in, const int* in_sizes, int n_in,
                              void* d_out, int out_size) {
    const float* X       = (const float*)d_in[0];
    const int*   ei      = (const int*)  d_in[1];
    const float* Wl      = (const float*)d_in[2];
    const float* Wr      = (const float*)d_in[3];
    const float* att     = (const float*)d_in[4];
    const float* gat_b   = (const float*)d_in[5];
    const float* W_time  = (const float*)d_in[6];
    const float* b_time  = (const float*)d_in[7];
    const float* W_res   = (const float*)d_in[8];
    const float* b_res   = (const float*)d_in[9];
    const float* ln_g    = (const float*)d_in[10];
    const float* ln_b    = (const float*)d_in[11];
    const float* W_final = (const float*)d_in[12];
    const float* b_final = (const float*)d_in[13];
    float* out = (float*)d_out;

    // k_score at launch slot 4 (the observed ncu capture slot)
    k_build<<<T, 1024>>>(ei);
    k_transpose<<<P, 256>>>(X);
    k_proj<<<T * P / 64, 256>>>(Wl, Wr);
    k_score<<<T * E / 32, 256>>>(ei, att);
    k_place<<<T * E / 256, 256>>>(ei);
    k_combine<<<T * P / 8, 256>>>(gat_b);
    k_epi<<<T * P / 64, 256>>>(W_time, b_time, W_res, b_res, ln_g, ln_b);
    k_final<<<P / 8, 256>>>(W_final, b_final, out);
}

// round 15
// speedup vs baseline: 1.0906x; 1.0906x over previous
#include <cuda_runtime.h>

#define FULL 0xffffffffu

constexpr int P = 4096, F = 64, HG = 64, C = 64, T = 32, E = 65536, HOUT = 12;
constexpr float EPS = 1e-5f;

// ---- scratch (static device globals; no allocation at runtime) ----
__device__ float  g_Xt[T * P * F];     // X transposed: [t][p][f]
__device__ float  g_hl[T * P * HG];    // x @ Wl
__device__ float  g_hr[T * P * HG];    // x @ Wr
__device__ int    g_deg[T * P];
__device__ int    g_offs[T * P];
__device__ int    g_cur[T * P];        // absolute write cursor (init = offs)
__device__ float  g_sc[T * E];         // raw scores, NATURAL edge order
__device__ float2 g_epair[T * E];      // CSR-ordered (src_as_float, score)
__device__ float  g_Xhat[T * P * HG];  // relu(GAT out)
__device__ float  g_yn[P * T * C];     // LayerNormed y, [p][t][c]

__device__ __forceinline__ float leaky(float x) { return x > 0.f ? x : 0.2f * x; }

__device__ __forceinline__ float warp_sum(float v) {
    v += __shfl_xor_sync(FULL, v, 16);
    v += __shfl_xor_sync(FULL, v, 8);
    v += __shfl_xor_sync(FULL, v, 4);
    v += __shfl_xor_sync(FULL, v, 2);
    v += __shfl_xor_sync(FULL, v, 1);
    return v;
}

__device__ __forceinline__ float warp_max(float v) {
    v = fmaxf(v, __shfl_xor_sync(FULL, v, 16));
    v = fmaxf(v, __shfl_xor_sync(FULL, v, 8));
    v = fmaxf(v, __shfl_xor_sync(FULL, v, 4));
    v = fmaxf(v, __shfl_xor_sync(FULL, v, 2));
    v = fmaxf(v, __shfl_xor_sync(FULL, v, 1));
    return v;
}

// dual FMA on float2 (plain C++; compiler emits 2x FFMA)
__device__ __forceinline__ void ffma2(float2& d, float b, float2 w) {
    d.x = fmaf(b, w.x, d.x);
    d.y = fmaf(b, w.y, d.y);
}

// ---- K1: zero + histogram + exclusive scan; cursor pre-set to offs ----
__global__ void __launch_bounds__(1024) k_build(const int* __restrict__ ei) {
    __shared__ int h[P];
    __shared__ int ssum[1024];
    int t = blockIdx.x, tid = threadIdx.x;
    for (int i = tid; i < P; i += 1024) h[i] = 0;
    __syncthreads();
    const int* dstp = ei + (size_t)t * 2 * E + E;
#pragma unroll 4
    for (int k = 0; k < 64; k++) atomicAdd(&h[dstp[k * 1024 + tid]], 1);
    __syncthreads();
    int base = tid * 4;
    int d0 = h[base], d1 = h[base + 1], d2 = h[base + 2], d3 = h[base + 3];
    ssum[tid] = d0 + d1 + d2 + d3;
    __syncthreads();
    for (int off = 1; off < 1024; off <<= 1) {
        int v = (tid >= off) ? ssum[tid - off] : 0;
        __syncthreads();
        ssum[tid] += v;
        __syncthreads();
    }
    int excl = tid ? ssum[tid - 1] : 0;
    int gb = t * P + base;
    int o0 = excl, o1 = excl + d0, o2 = o1 + d1, o3 = o2 + d2;
    g_offs[gb] = o0; g_offs[gb + 1] = o1; g_offs[gb + 2] = o2; g_offs[gb + 3] = o3;
    g_deg[gb] = d0;  g_deg[gb + 1] = d1;  g_deg[gb + 2] = d2;  g_deg[gb + 3] = d3;
    g_cur[gb] = o0;  g_cur[gb + 1] = o1;  g_cur[gb + 2] = o2;  g_cur[gb + 3] = o3;
}

// ---- K2: transpose X[1,P,F,T] -> Xt[t][p][f] ----
__global__ void k_transpose(const float* __restrict__ X) {
    __shared__ float sm[64 * 33];
    int p = blockIdx.x;
    const float* xp = X + (size_t)p * (F * T);
    for (int idx = threadIdx.x; idx < F * T; idx += blockDim.x) {
        int f = idx >> 5, t = idx & 31;
        sm[f * 33 + t] = xp[idx];
    }
    __syncthreads();
    for (int idx = threadIdx.x; idx < F * T; idx += blockDim.x) {
        int t = idx >> 6, f = idx & 63;
        g_Xt[((size_t)t * P + p) * 64 + f] = sm[f * 33 + t];
    }
}

// ---- K3: hl = x@Wl, hr = x@Wr  (warp per 8 rows, float2 LDS) ----
__global__ void __launch_bounds__(256) k_proj(const float* __restrict__ Wl,
                                              const float* __restrict__ Wr) {
    __shared__ float2 sWl[2048], sWr[2048];   // [k][col-pair] (row-major (F,HG))
    for (int i = threadIdx.x; i < 2048; i += blockDim.x) {
        sWl[i] = ((const float2*)Wl)[i];
        sWr[i] = ((const float2*)Wr)[i];
    }
    __syncthreads();
    int w = blockIdx.x * 8 + (threadIdx.x >> 5);
    int lane = threadIdx.x & 31;
    int row0 = w * 8;
    float x0[8], x1[8];
#pragma unroll
    for (int r = 0; r < 8; r++) {
        const float* x = g_Xt + (size_t)(row0 + r) * 64;
        x0[r] = x[lane]; x1[r] = x[lane + 32];
    }
    float2 al[8], ar[8];
#pragma unroll
    for (int r = 0; r < 8; r++) { al[r] = make_float2(0.f, 0.f); ar[r] = make_float2(0.f, 0.f); }
#pragma unroll 4
    for (int k = 0; k < 32; k++) {
        float2 wl = sWl[k * 32 + lane], wr = sWr[k * 32 + lane];
#pragma unroll
        for (int r = 0; r < 8; r++) {
            float b = __shfl_sync(FULL, x0[r], k);
            ffma2(al[r], b, wl);
            ffma2(ar[r], b, wr);
        }
    }
#pragma unroll 4
    for (int k = 0; k < 32; k++) {
        float2 wl = sWl[(k + 32) * 32 + lane], wr = sWr[(k + 32) * 32 + lane];
#pragma unroll
        for (int r = 0; r < 8; r++) {
            float b = __shfl_sync(FULL, x1[r], k);
            ffma2(al[r], b, wl);
            ffma2(ar[r], b, wr);
        }
    }
#pragma unroll
    for (int r = 0; r < 8; r++) {
        ((float2*)g_hl)[(size_t)(row0 + r) * 32 + lane] = al[r];
        ((float2*)g_hr)[(size_t)(row0 + r) * 32 + lane] = ar[r];
    }
}

// ---- K4: scoring, natural edge order, 8 edges/warp (2 per oct) for MLP ----
__global__ void __launch_bounds__(256) k_score(const int* __restrict__ ei,
                                               const float* __restrict__ att) {
    int lane = threadIdx.x & 31;
    int oct = lane >> 3, sub = lane & 7;
    int warp = blockIdx.x * 8 + (threadIdx.x >> 5);
    int t = warp >> 13;                     // E/8 = 8192 warps per t
    int e0 = (warp & 8191) * 8 + oct;       // edges e0 and e0+4
    size_t tb = (size_t)t * 2 * E;
    int src0 = ei[tb + e0],     dst0 = ei[tb + E + e0];
    int src1 = ei[tb + e0 + 4], dst1 = ei[tb + E + e0 + 4];
    const float4* hbase = (const float4*)g_hl + (size_t)t * P * 16;
    const float4* rbase = (const float4*)g_hr + (size_t)t * P * 16;
    const float4* at4 = (const float4*)att;
    float sc0 = 0.f, sc1 = 0.f;
#pragma unroll
    for (int k = 0; k < 2; k++) {
        int idx = sub + 8 * k;
        float4 a = at4[idx];
        float4 vl0 = hbase[(size_t)src0 * 16 + idx];
        float4 vr0 = rbase[(size_t)dst0 * 16 + idx];
        float4 vl1 = hbase[(size_t)src1 * 16 + idx];
        float4 vr1 = rbase[(size_t)dst1 * 16 + idx];
        sc0 += leaky(vl0.x + vr0.x) * a.x + leaky(vl0.y + vr0.y) * a.y
             + leaky(vl0.z + vr0.z) * a.z + leaky(vl0.w + vr0.w) * a.w;
        sc1 += leaky(vl1.x + vr1.x) * a.x + leaky(vl1.y + vr1.y) * a.y
             + leaky(vl1.z + vr1.z) * a.z + leaky(vl1.w + vr1.w) * a.w;
    }
    sc0 += __shfl_xor_sync(FULL, sc0, 4);
    sc1 += __shfl_xor_sync(FULL, sc1, 4);
    sc0 += __shfl_xor_sync(FULL, sc0, 2);
    sc1 += __shfl_xor_sync(FULL, sc1, 2);
    sc0 += __shfl_xor_sync(FULL, sc0, 1);
    sc1 += __shfl_xor_sync(FULL, sc1, 1);
    if (sub == 0) {
        g_sc[(size_t)t * E + e0] = sc0;
        g_sc[(size_t)t * E + e0 + 4] = sc1;
    }
}

// ---- K5: place packed (src, score) into CSR buckets (one STG.64 per edge) ----
__global__ void k_place(const int* __restrict__ ei) {
    int gid = blockIdx.x * blockDim.x + threadIdx.x;
    int t = gid >> 16, e = gid & (E - 1);
    int src = ei[(size_t)t * 2 * E + e];
    int dst = ei[(size_t)t * 2 * E + E + e];
    float sc = g_sc[(size_t)t * E + e];
    int slot = atomicAdd(&g_cur[t * P + dst], 1);   // absolute (cursor = offs)
    g_epair[(size_t)t * E + slot] = make_float2(__int_as_float(src), sc);
}

// ---- K6: softmax + weighted gather; only ceil(deg/2) iterations ----
__global__ void __launch_bounds__(256) k_combine(const float* __restrict__ gat_b) {
    int lane = threadIdx.x & 31;
    int half = lane >> 4, hlane = lane & 15;
    int warp = blockIdx.x * 8 + (threadIdx.x >> 5);
    int t = warp >> 12;
    int start = g_offs[warp], deg = g_deg[warp];
    const float2* ep = g_epair + (size_t)t * E + start;
    const float4* hl4 = (const float4*)g_hl + (size_t)t * P * 16;
    float4 acc = make_float4(0.f, 0.f, 0.f, 0.f);
    float inv = 0.f;

    if (deg <= 32) {
        float2 pr = (lane < deg) ? ep[lane] : make_float2(0.f, -1e30f);
        int srcs = (lane < deg) ? __float_as_int(pr.x) : 0;
        float mx = warp_max(pr.y);
        float wgt = (lane < deg) ? __expf(pr.y - mx) : 0.f;
        float s = warp_sum(wgt);
        int iters = (deg + 1) >> 1;           // 2 edges/iter, no dummy tail
#pragma unroll 4
        for (int jj = 0; jj < iters; jj++) {
            int j = jj * 2 + half;            // j<=32; odd-deg tail has wgt 0
            int sj = __shfl_sync(FULL, srcs, j & 31);
            float wj = __shfl_sync(FULL, wgt, j & 31);
            float4 v = hl4[(size_t)sj * 16 + hlane];
            acc.x += wj * v.x; acc.y += wj * v.y;
            acc.z += wj * v.z; acc.w += wj * v.w;
        }
        inv = (deg > 0) ? 1.f / s : 0.f;
    } else {
        float mx = -1e30f;
        for (int i = lane; i < deg; i += 32) mx = fmaxf(mx, ep[i].y);
        mx = warp_max(mx);
        float s = 0.f;
        for (int k = 0; k < deg; k += 32) {
            int n = min(32, deg - k);
            float2 pr = (lane < n) ? ep[k + lane] : make_float2(0.f, -1e30f);
            int srcs = (lane < n) ? __float_as_int(pr.x) : 0;
            float wgt = (lane < n) ? __expf(pr.y - mx) : 0.f;
            s += wgt;
            int iters = (n + 1) >> 1;
#pragma unroll 4
            for (int jj = 0; jj < iters; jj++) {
                int j = jj * 2 + half;
                int sj = __shfl_sync(FULL, srcs, j & 31);
                float wj = __shfl_sync(FULL, wgt, j & 31);
                float4 v = hl4[(size_t)sj * 16 + hlane];
                acc.x += wj * v.x; acc.y += wj * v.y;
                acc.z += wj * v.z; acc.w += wj * v.w;
            }
        }
        s = warp_sum(s);
        inv = 1.f / s;
    }
    acc.x += __shfl_xor_sync(FULL, acc.x, 16);
    acc.y += __shfl_xor_sync(FULL, acc.y, 16);
    acc.z += __shfl_xor_sync(FULL, acc.z, 16);
    acc.w += __shfl_xor_sync(FULL, acc.w, 16);
    if (half == 0) {
        float4 gb = ((const float4*)gat_b)[hlane];
        float4 o;
        o.x = fmaxf(acc.x * inv + gb.x, 0.f);
        o.y = fmaxf(acc.y * inv + gb.y, 0.f);
        o.z = fmaxf(acc.z * inv + gb.z, 0.f);
        o.w = fmaxf(acc.w * inv + gb.w, 0.f);
        ((float4*)g_Xhat)[(size_t)warp * 16 + hlane] = o;
    }
}

// ---- K7: time conv + residual conv + relu + LayerNorm (warp per 8 rows) ----
__global__ void __launch_bounds__(256) k_epi(const float* __restrict__ Wt, const float* __restrict__ bt,
                                             const float* __restrict__ Wr_, const float* __restrict__ br,
                                             const float* __restrict__ lng, const float* __restrict__ lnb) {
    __shared__ float sWt[64 * 66], sWr[64 * 66];   // [h][c], pad 66
    for (int idx = threadIdx.x; idx < 4096; idx += blockDim.x) {
        int c = idx >> 6, h = idx & 63;
        sWt[h * 66 + c] = Wt[idx];                 // W_time (C, HG) row-major
        sWr[h * 66 + c] = Wr_[idx];                // W_res  (C, F)  row-major
    }
    __syncthreads();
    int w = blockIdx.x * 8 + (threadIdx.x >> 5);
    int lane = threadIdx.x & 31;
    int row0 = w * 8;
    int t = row0 >> 12;
    float xh0[8], xh1[8], xf0[8], xf1[8];
#pragma unroll
    for (int r = 0; r < 8; r++) {
        size_t base = (size_t)(row0 + r) * 64;
        xh0[r] = g_Xhat[base + lane]; xh1[r] = g_Xhat[base + lane + 32];
        xf0[r] = g_Xt[base + lane];   xf1[r] = g_Xt[base + lane + 32];
    }
    float2 th[8], rs[8];
#pragma unroll
    for (int r = 0; r < 8; r++) { th[r] = make_float2(0.f, 0.f); rs[r] = make_float2(0.f, 0.f); }
#pragma unroll 4
    for (int k = 0; k < 32; k++) {
        float2 wt = *(const float2*)(sWt + k * 66 + 2 * lane);
        float2 wr = *(const float2*)(sWr + k * 66 + 2 * lane);
#pragma unroll
        for (int r = 0; r < 8; r++) {
            float bh = __shfl_sync(FULL, xh0[r], k);
            float bf = __shfl_sync(FULL, xf0[r], k);
            ffma2(th[r], bh, wt);
            ffma2(rs[r], bf, wr);
        }
    }
#pragma unroll 4
    for (int k = 0; k < 32; k++) {
        float2 wt = *(const float2*)(sWt + (k + 32) * 66 + 2 * lane);
        float2 wr = *(const float2*)(sWr + (k + 32) * 66 + 2 * lane);
#pragma unroll
        for (int r = 0; r < 8; r++) {
            float bh = __shfl_sync(FULL, xh1[r], k);
            float bf = __shfl_sync(FULL, xf1[r], k);
            ffma2(th[r], bh, wt);
            ffma2(rs[r], bf, wr);
        }
    }
    float2 btc = ((const float2*)bt)[lane];
    float2 brc = ((const float2*)br)[lane];
    float2 g2 = ((const float2*)lng)[lane];
    float2 lb2 = ((const float2*)lnb)[lane];
    float bsx = btc.x + brc.x, bsy = btc.y + brc.y;
#pragma unroll
    for (int r = 0; r < 8; r++) {
        float y0 = fmaxf(th[r].x + rs[r].x + bsx, 0.f);
        float y1 = fmaxf(th[r].y + rs[r].y + bsy, 0.f);
        float mu = warp_sum(y0 + y1) * (1.f / 64.f);
        float d0 = y0 - mu, d1 = y1 - mu;
        float var = warp_sum(d0 * d0 + d1 * d1) * (1.f / 64.f);
        float rq = rsqrtf(var + EPS);
        int p = (row0 + r) & (P - 1);
        float2 yn2;
        yn2.x = d0 * rq * g2.x + lb2.x;
        yn2.y = d1 * rq * g2.y + lb2.y;
        ((float2*)(g_yn + (size_t)p * (T * C) + t * 64))[lane] = yn2;
    }
}

// ---- K8: final contraction out[p][o] = sum_{t,c} yn[p][t][c] * Wf[o][t][c] ----
__global__ void k_final(const float* __restrict__ Wf, const float* __restrict__ bf,
                        float* __restrict__ out) {
    int warp = blockIdx.x * (blockDim.x >> 5) + (threadIdx.x >> 5);
    int lane = threadIdx.x & 31;
    int p = warp;
    const float* y = g_yn + (size_t)p * (T * C);
    float acc[HOUT];
#pragma unroll
    for (int o = 0; o < HOUT; o++) acc[o] = 0.f;
    for (int idx = lane; idx < T * C; idx += 32) {
        float yv = y[idx];
#pragma unroll
        for (int o = 0; o < HOUT; o++) acc[o] += yv * __ldg(&Wf[o * (T * C) + idx]);
    }
    float myval = 0.f;
#pragma unroll
    for (int o = 0; o < HOUT; o++) {
        float v = warp_sum(acc[o]);
        if (lane == o) myval = v;
    }
    if (lane < HOUT) out[p * HOUT + lane] = myval + __ldg(&bf[lane]);
}

extern "C" void kernel_launch(void* const* d_in, const int* in_sizes, int n_in,
                              void* d_out, int out_size) {
    const float* X       = (const float*)d_in[0];
    const int*   ei      = (const int*)  d_in[1];
    const float* Wl      = (const float*)d_in[2];
    const float* Wr      = (const float*)d_in[3];
    const float* att     = (const float*)d_in[4];
    const float* gat_b   = (const float*)d_in[5];
    const float* W_time  = (const float*)d_in[6];
    const float* b_time  = (const float*)d_in[7];
    const float* W_res   = (const float*)d_in[8];
    const float* b_res   = (const float*)d_in[9];
    const float* ln_g    = (const float*)d_in[10];
    const float* ln_b    = (const float*)d_in[11];
    const float* W_final = (const float*)d_in[12];
    const float* b_final = (const float*)d_in[13];
    float* out = (float*)d_out;

    // k_score at launch slot 4 (the observed ncu capture slot)
    k_build<<<T, 1024>>>(ei);
    k_transpose<<<P, 256>>>(X);
    k_proj<<<T * P / 64, 256>>>(Wl, Wr);
    k_score<<<T * E / 64, 256>>>(ei, att);
    k_place<<<T * E / 256, 256>>>(ei);
    k_combine<<<T * P / 8, 256>>>(gat_b);
    k_epi<<<T * P / 64, 256>>>(W_time, b_time, W_res, b_res, ln_g, ln_b);
    k_final<<<P / 8, 256>>>(W_final, b_final, out);
}